// round 14
// baseline (speedup 1.0000x reference)
#include <cuda_runtime.h>
#include <cuda_bf16.h>
#include <math.h>
#include <stdint.h>

// Problem constants (fixed by the reference)
#define NNODES 10000
#define NEDGES 320000
#define DIN    512
#define DHID   2048
#define NCLS   40

#define GA_ROWS 10112             // 79 * 128 (padded M; pad rows stay zero)

// GEMM1: A'[M x 1024]=[hi|lo], B'(W1^T)[2048 x 1536]=[hi|lo|hi], 24 K-chunks
#define KA1     1024
#define KB1     1536
#define BM      128
#define BN      128
#define BK      64                // 64 bf16 = 128 B per SMEM row
#define NKIT    24

#define KA2     4096              // W2' row width: [hi(2048) | lo(2048)]
#define NCP     48                // padded class count

// prep_init block ranges
#define PREP_W2_BLOCKS   NCP                          // 48
#define PREP_W1_BLOCKS   ((DIN / 32) * (DHID / 32))   // 1024
#define PREP_CNT_BLOCKS  ((NEDGES + 255) / 256)       // 1250
#define PREP_TOTAL_BLOCKS (PREP_W2_BLOCKS + PREP_W1_BLOCKS + PREP_CNT_BLOCKS)

// ---------------------------------------------------------------------------
// Device scratch (static globals: no runtime allocation allowed)
// g_cnt is zero at module load; scan_kernel re-zeroes it after use, so it is
// all-zero at the entry of EVERY kernel_launch call (incl. graph replays).
// ---------------------------------------------------------------------------
__device__ int   g_cnt[NNODES];
__device__ int   g_rowptr[NNODES + 1];
__device__ int   g_cursor[NNODES];
__device__ float g_dinv[NNODES];
__device__ int   g_csr_src[NEDGES];
__device__ float g_csr_coef[NEDGES];
__device__ __nv_bfloat16 g_Abf[(size_t)GA_ROWS * KA1];   // 20.7 MB
__device__ __nv_bfloat16 g_Bbf[(size_t)DHID * KB1];      // 6.3 MB
__device__ __nv_bfloat16 g_W2bf[(size_t)NCP * KA2];      // 393 KB
__device__ float g_tp[32][(size_t)NNODES * NCP];         // 61.4 MB partials
__device__ float g_t[(size_t)NNODES * NCLS];             // 1.6 MB

// ---------------------------------------------------------------------------
// PTX helpers
// ---------------------------------------------------------------------------
__device__ __forceinline__ uint32_t smem_u32(const void* p) {
    uint32_t a;
    asm("{ .reg .u64 t; cvta.to.shared.u64 t, %1; cvt.u32.u64 %0, t; }"
        : "=r"(a) : "l"(p));
    return a;
}
__device__ __forceinline__ void cp_async16(uint32_t saddr, const void* gaddr) {
    asm volatile("cp.async.cg.shared.global [%0], [%1], 16;"
                 :: "r"(saddr), "l"(gaddr) : "memory");
}
__device__ __forceinline__ void cp_commit() {
    asm volatile("cp.async.commit_group;" ::: "memory");
}
template <int N>
__device__ __forceinline__ void cp_wait() {
    asm volatile("cp.async.wait_group %0;" :: "n"(N) : "memory");
}
__device__ __forceinline__ void ldsm_x4(uint32_t addr, uint32_t& r0, uint32_t& r1,
                                        uint32_t& r2, uint32_t& r3) {
    asm volatile("ldmatrix.sync.aligned.m8n8.x4.shared.b16 {%0,%1,%2,%3}, [%4];"
                 : "=r"(r0), "=r"(r1), "=r"(r2), "=r"(r3) : "r"(addr));
}
__device__ __forceinline__ void mma_bf16(float* d, const uint32_t* a, const uint32_t* b) {
    asm volatile(
        "mma.sync.aligned.m16n8k16.row.col.f32.bf16.bf16.f32 "
        "{%0,%1,%2,%3}, {%4,%5,%6,%7}, {%8,%9}, {%0,%1,%2,%3};"
        : "+f"(d[0]), "+f"(d[1]), "+f"(d[2]), "+f"(d[3])
        : "r"(a[0]), "r"(a[1]), "r"(a[2]), "r"(a[3]), "r"(b[0]), "r"(b[1]));
}
__device__ __forceinline__ void stcs_f2(void* p, float a, float b) {
    asm volatile("st.global.cs.v2.f32 [%0], {%1, %2};"
                 :: "l"(p), "f"(a), "f"(b) : "memory");
}
// pack two fp32 -> bf16x2 (v0 in low half), and produce the lo-residual pack
__device__ __forceinline__ uint32_t pack_split(float v0, float v1, uint32_t& loOut) {
    uint32_t hi;
    asm("cvt.rn.bf16x2.f32 %0, %1, %2;" : "=r"(hi) : "f"(v1), "f"(v0));
    float h0 = __uint_as_float(hi << 16);
    float h1 = __uint_as_float(hi & 0xffff0000u);
    float l0 = v0 - h0, l1 = v1 - h1;
    asm("cvt.rn.bf16x2.f32 %0, %1, %2;" : "=r"(loOut) : "f"(l1), "f"(l0));
    return hi;
}

// ---------------------------------------------------------------------------
// Fused init + count:
//   blocks [0, 48):        W2' rows (hi|lo)
//   blocks [48, 1072):     W1 transpose+split tiles (16 x 64 tiles of 32x32)
//   blocks [1072, 2322):   degree histogram (g_cnt pre-zeroed — see above)
// ---------------------------------------------------------------------------
__global__ void prep_init_kernel(const float* __restrict__ W1,
                                 const float* __restrict__ W2,
                                 const int* __restrict__ dst) {
    __shared__ float tile[32][33];
    int b = blockIdx.x;
    int tid = threadIdx.x;
    if (b < PREP_W2_BLOCKS) {
        int n = b;
        __nv_bfloat16* row = &g_W2bf[(size_t)n * KA2];
        for (int k = tid; k < DHID; k += blockDim.x) {
            float w = (n < NCLS) ? W2[(size_t)k * NCLS + n] : 0.0f;
            __nv_bfloat16 hi = __float2bfloat16(w);
            __nv_bfloat16 lo = __float2bfloat16(w - __bfloat162float(hi));
            row[k]        = hi;
            row[2048 + k] = lo;
        }
    } else if (b < PREP_W2_BLOCKS + PREP_W1_BLOCKS) {
        int tb = b - PREP_W2_BLOCKS;               // 0..1023
        int k0 = (tb & 15) * 32;                   // DIN/32 = 16
        int n0 = (tb >> 4) * 32;                   // DHID/32 = 64
        int tx = tid & 31, ty = tid >> 5;          // (32, 8)
        #pragma unroll
        for (int j = 0; j < 4; j++)
            tile[ty + 8 * j][tx] = W1[(size_t)(k0 + ty + 8 * j) * DHID + n0 + tx];
        __syncthreads();
        #pragma unroll
        for (int j = 0; j < 4; j++) {
            int n = n0 + ty + 8 * j;
            int k = k0 + tx;
            float w = tile[tx][ty + 8 * j];
            __nv_bfloat16 hi = __float2bfloat16(w);
            __nv_bfloat16 lo = __float2bfloat16(w - __bfloat162float(hi));
            __nv_bfloat16* row = &g_Bbf[(size_t)n * KB1];
            row[k]        = hi;
            row[512 + k]  = lo;
            row[1024 + k] = hi;
        }
    } else {
        int e = (b - PREP_W2_BLOCKS - PREP_W1_BLOCKS) * 256 + tid;
        if (e < NEDGES) atomicAdd(&g_cnt[dst[e]], 1);
    }
}

// Single-block warp-shuffle scan + dinv + cursor.
// Re-zeroes g_cnt after consuming it (keeps the entry invariant for the
// count blocks of prep_init_kernel on the next call / graph replay).
__global__ void scan_kernel() {
    __shared__ int warp_sums[32];
    __shared__ int s_carry;
    int tid = threadIdx.x, lane = tid & 31, w = tid >> 5;
    if (tid == 0) { s_carry = 0; g_rowptr[0] = 0; }
    __syncthreads();
    for (int base = 0; base < NNODES; base += 1024) {
        int i = base + tid;
        int v = (i < NNODES) ? g_cnt[i] : 0;
        if (i < NNODES) g_cnt[i] = 0;     // recycle for next run
        int x = v;
        #pragma unroll
        for (int off = 1; off < 32; off <<= 1) {
            int t = __shfl_up_sync(0xFFFFFFFFu, x, off);
            if (lane >= off) x += t;
        }
        if (lane == 31) warp_sums[w] = x;
        __syncthreads();
        if (w == 0) {
            int s = warp_sums[lane];
            #pragma unroll
            for (int off = 1; off < 32; off <<= 1) {
                int t = __shfl_up_sync(0xFFFFFFFFu, s, off);
                if (lane >= off) s += t;
            }
            warp_sums[lane] = s;
        }
        __syncthreads();
        int warp_off = (w > 0) ? warp_sums[w - 1] : 0;
        int incl = x + warp_off + s_carry;
        if (i < NNODES) {
            g_rowptr[i + 1] = incl;
            g_cursor[i]     = incl - v;
            g_dinv[i]       = rsqrtf((float)v + 1.0f);
        }
        __syncthreads();
        if (tid == 0) s_carry += warp_sums[31];
        __syncthreads();
    }
}

__global__ void fill_kernel(const int* __restrict__ src, const int* __restrict__ dst) {
    int e = blockIdx.x * blockDim.x + threadIdx.x;
    if (e >= NEDGES) return;
    int s = src[e], d = dst[e];
    int p = atomicAdd(&g_cursor[d], 1);
    g_csr_src[p]  = s;
    g_csr_coef[p] = g_dinv[s] * g_dinv[d];
}

// ---------------------------------------------------------------------------
// Layer-1 propagate + split pack: A'[i] = [hi | lo]
// Edge (src, coef) pairs staged in SMEM (coalesced load, broadcast LDS reads),
// x-row loads unrolled x4 for MLP.
// ---------------------------------------------------------------------------
__global__ void gather1_kernel(const float* __restrict__ x) {
    __shared__ int2 s_edge[128];
    int i = blockIdx.x;
    int tid = threadIdx.x;
    float di = g_dinv[i];
    float self = di * di;
    float4 xv = ((const float4*)&x[(size_t)i * DIN])[tid];
    float4 acc;
    acc.x = self * xv.x; acc.y = self * xv.y;
    acc.z = self * xv.z; acc.w = self * xv.w;
    int beg = g_rowptr[i], end = g_rowptr[i + 1];

    for (int base = beg; base < end; base += 128) {
        int n = end - base;
        if (n > 128) n = 128;
        if (tid < n)
            s_edge[tid] = make_int2(g_csr_src[base + tid],
                                    __float_as_int(g_csr_coef[base + tid]));
        __syncthreads();
        int j = 0;
        for (; j + 3 < n; j += 4) {
            int2 e0 = s_edge[j + 0];
            int2 e1 = s_edge[j + 1];
            int2 e2 = s_edge[j + 2];
            int2 e3 = s_edge[j + 3];
            float4 v0 = ((const float4*)&x[(size_t)e0.x * DIN])[tid];
            float4 v1 = ((const float4*)&x[(size_t)e1.x * DIN])[tid];
            float4 v2 = ((const float4*)&x[(size_t)e2.x * DIN])[tid];
            float4 v3 = ((const float4*)&x[(size_t)e3.x * DIN])[tid];
            float c0 = __int_as_float(e0.y), c1 = __int_as_float(e1.y);
            float c2 = __int_as_float(e2.y), c3 = __int_as_float(e3.y);
            acc.x += c0 * v0.x + c1 * v1.x + c2 * v2.x + c3 * v3.x;
            acc.y += c0 * v0.y + c1 * v1.y + c2 * v2.y + c3 * v3.y;
            acc.z += c0 * v0.z + c1 * v1.z + c2 * v2.z + c3 * v3.z;
            acc.w += c0 * v0.w + c1 * v1.w + c2 * v2.w + c3 * v3.w;
        }
        for (; j < n; j++) {
            int2 e = s_edge[j];
            float c = __int_as_float(e.y);
            float4 v = ((const float4*)&x[(size_t)e.x * DIN])[tid];
            acc.x += c * v.x; acc.y += c * v.y;
            acc.z += c * v.z; acc.w += c * v.w;
        }
        __syncthreads();
    }

    float a[4] = {acc.x, acc.y, acc.z, acc.w};
    union { __nv_bfloat16 h[4]; uint2 u; } hp, lp;
    #pragma unroll
    for (int t = 0; t < 4; t++) {
        hp.h[t] = __float2bfloat16(a[t]);
        lp.h[t] = __float2bfloat16(a[t] - __bfloat162float(hp.h[t]));
    }
    int k = tid * 4;
    __nv_bfloat16* row = &g_Abf[(size_t)i * KA1];
    *(uint2*)&row[k]       = hp.u;
    *(uint2*)&row[512 + k] = lp.u;
}

// ---------------------------------------------------------------------------
// Fused GEMM1+GEMM2 (mma.sync bf16):
//   h_block = relu(A' @ B'^T + b1)   (fp32 in registers, never materialized)
//   partial[c] = h_block @ W2_slice  (3-term split, A-frags built from C-frags)
// 128x128x64 CTA tile, 128 threads (4 warps, 2x2, warp tile 64x64), 3-stage
// pipeline, occ 2. Each warp writes a [64 x 48] fp32 partial into slice
// (blockIdx.x*2 + warp_n); combine_kernel sums the 32 slices.
// ---------------------------------------------------------------------------
#define STAGE_BYTES (BM * BK * 2 + BN * BK * 2)   // 32768
#define GEMM1_SMEM  (3 * STAGE_BYTES)             // 98304

__global__ __launch_bounds__(128, 2)
void gemm_fused_kernel(const float* __restrict__ bias) {
    extern __shared__ char dsm[];
    const uint32_t sbase = smem_u32(dsm);
    const int tid  = threadIdx.x;
    const int wid  = tid >> 5;
    const int lane = tid & 31;
    const int warp_m = wid & 1;
    const int warp_n = wid >> 1;
    const int block_n = blockIdx.x * BN;
    const int block_m = blockIdx.y * BM;

    uint32_t sA[3], sB[3];
    #pragma unroll
    for (int s = 0; s < 3; s++) {
        sA[s] = sbase + s * STAGE_BYTES;
        sB[s] = sA[s] + (uint32_t)(BM * BK * 2);
    }

    auto load_stage = [&](int kt, int s) {
        const int ka = ((kt < 8) ? kt : kt - 8) * BK;
        const int kb = kt * BK;
        #pragma unroll
        for (int i = 0; i < 8; i++) {
            int t = tid + i * 128;
            int row = t >> 3, c = t & 7;
            uint32_t sw = (uint32_t)(row << 7) + (uint32_t)(((c ^ (row & 7)) << 4));
            cp_async16(sA[s] + sw, &g_Abf[(size_t)(block_m + row) * KA1 + ka + c * 8]);
        }
        #pragma unroll
        for (int i = 0; i < 8; i++) {
            int t = tid + i * 128;
            int row = t >> 3, c = t & 7;
            uint32_t sw = (uint32_t)(row << 7) + (uint32_t)(((c ^ (row & 7)) << 4));
            cp_async16(sB[s] + sw, &g_Bbf[(size_t)(block_n + row) * KB1 + kb + c * 8]);
        }
        cp_commit();
    };

    const int grp  = lane >> 3;
    const int lrow = lane & 7;
    const int arow_base = warp_m * 64 + ((grp & 1) << 3) + lrow;
    const int akc_half = grp >> 1;
    const int brow_base = warp_n * 64 + ((grp >> 1) << 3) + lrow;
    const int bkc_half = grp & 1;

    float acc[4][8][4];
    #pragma unroll
    for (int i = 0; i < 4; i++)
        #pragma unroll
        for (int j = 0; j < 8; j++)
            #pragma unroll
            for (int q = 0; q < 4; q++) acc[i][j][q] = 0.0f;

    load_stage(0, 0);
    load_stage(1, 1);

    for (int kt = 0; kt < NKIT; kt++) {
        const int cur = kt % 3;
        if (kt < NKIT - 1) cp_wait<1>();
        else               cp_wait<0>();
        __syncthreads();
        if (kt + 2 < NKIT) load_stage(kt + 2, (kt + 2) % 3);

        #pragma unroll
        for (int ks = 0; ks < 4; ks++) {
            uint32_t a[4][4];
            const int kca = 2 * ks + akc_half;
            #pragma unroll
            for (int mt = 0; mt < 4; mt++) {
                const int arow = arow_base + mt * 16;
                ldsm_x4(sA[cur] + (uint32_t)(arow << 7) + (uint32_t)(((kca ^ (arow & 7)) << 4)),
                        a[mt][0], a[mt][1], a[mt][2], a[mt][3]);
            }
            const int kcb = 2 * ks + bkc_half;
            uint32_t b[4][4];
            #pragma unroll
            for (int p = 0; p < 4; p++) {
                const int brow = brow_base + p * 16;
                ldsm_x4(sB[cur] + (uint32_t)(brow << 7) + (uint32_t)(((kcb ^ (brow & 7)) << 4)),
                        b[p][0], b[p][1], b[p][2], b[p][3]);
            }
            #pragma unroll
            for (int mt = 0; mt < 4; mt++)
                #pragma unroll
                for (int p = 0; p < 4; p++) {
                    mma_bf16(acc[mt][2 * p + 0], a[mt], &b[p][0]);
                    mma_bf16(acc[mt][2 * p + 1], a[mt], &b[p][2]);
                }
        }
    }

    // ------- Fused epilogue: partial = relu(acc+b1) @ W2_slice -------
    __syncthreads();   // everyone done with pipeline smem
    const uint32_t sW = sbase;
    #pragma unroll
    for (int i = 0; i < 12; i++) {
        int t = tid + i * 128;                 // 0..1535
        int blk = (t >= 768) ? 1 : 0;
        int q = t - blk * 768;
        int row = q >> 4, c = q & 15;
        uint32_t sw = (uint32_t)((c & 8) | ((c ^ (row & 7)) & 7));
        cp_async16(sW + (uint32_t)(blk * 12288 + row * 256) + (sw << 4),
                   &g_W2bf[(size_t)row * KA2 + blk * 2048 + block_n + c * 8]);
    }
    cp_commit();
    cp_wait<0>();
    __syncthreads();

    const int grpID = lane >> 2;
    const int tg    = lane & 3;
    const int brow_lane = ((grp >> 1) << 3) + lrow;   // 0..15
    float* dst = g_tp[blockIdx.x * 2 + warp_n];

    #pragma unroll
    for (int mt = 0; mt < 4; mt++) {
        float t2[6][4];
        #pragma unroll
        for (int t = 0; t < 6; t++)
            #pragma unroll
            for (int q = 0; q < 4; q++) t2[t][q] = 0.0f;

        #pragma unroll
        for (int j = 0; j < 4; j++) {
            int colA = block_n + warp_n * 64 + 16 * j + tg * 2;
            float b00 = bias[colA],     b01 = bias[colA + 1];
            float b10 = bias[colA + 8], b11 = bias[colA + 9];
            float v00 = fmaxf(acc[mt][2 * j][0] + b00, 0.f);
            float v01 = fmaxf(acc[mt][2 * j][1] + b01, 0.f);
            float v02 = fmaxf(acc[mt][2 * j][2] + b00, 0.f);
            float v03 = fmaxf(acc[mt][2 * j][3] + b01, 0.f);
            float v10 = fmaxf(acc[mt][2 * j + 1][0] + b10, 0.f);
            float v11 = fmaxf(acc[mt][2 * j + 1][1] + b11, 0.f);
            float v12 = fmaxf(acc[mt][2 * j + 1][2] + b10, 0.f);
            float v13 = fmaxf(acc[mt][2 * j + 1][3] + b11, 0.f);

            uint32_t aHi[4], aLo[4];
            aHi[0] = pack_split(v00, v01, aLo[0]);
            aHi[1] = pack_split(v02, v03, aLo[1]);
            aHi[2] = pack_split(v10, v11, aLo[2]);
            aHi[3] = pack_split(v12, v13, aLo[3]);

            const int cfull = warp_n * 8 + 2 * j + bkc_half;   // 16B-chunk 0..15
            uint32_t bHi[3][4], bLo[3][4];
            #pragma unroll
            for (int p = 0; p < 3; p++) {
                const int brow = brow_lane + p * 16;
                uint32_t sw = (uint32_t)((cfull & 8) | ((cfull ^ (brow & 7)) & 7));
                uint32_t off = (uint32_t)(brow * 256) + (sw << 4);
                ldsm_x4(sW + off,         bHi[p][0], bHi[p][1], bHi[p][2], bHi[p][3]);
                ldsm_x4(sW + 12288 + off, bLo[p][0], bLo[p][1], bLo[p][2], bLo[p][3]);
            }
            #pragma unroll
            for (int p = 0; p < 3; p++) {
                mma_bf16(t2[2 * p + 0], aHi, &bHi[p][0]);
                mma_bf16(t2[2 * p + 1], aHi, &bHi[p][2]);
                mma_bf16(t2[2 * p + 0], aHi, &bLo[p][0]);
                mma_bf16(t2[2 * p + 1], aHi, &bLo[p][2]);
                mma_bf16(t2[2 * p + 0], aLo, &bHi[p][0]);
                mma_bf16(t2[2 * p + 1], aLo, &bHi[p][2]);
            }
        }

        const int r0 = block_m + warp_m * 64 + mt * 16 + grpID;
        const int r1 = r0 + 8;
        #pragma unroll
        for (int t = 0; t < 6; t++) {
            const int col = t * 8 + tg * 2;
            if (r0 < NNODES) stcs_f2(&dst[(size_t)r0 * NCP + col], t2[t][0], t2[t][1]);
            if (r1 < NNODES) stcs_f2(&dst[(size_t)r1 * NCP + col], t2[t][2], t2[t][3]);
        }
    }
}

// combine the 32 partial slices: g_t[r, 0..39] = sum_z g_tp[z][r, 0..39]
__global__ void combine_kernel() {
    int idx = blockIdx.x * blockDim.x + threadIdx.x;   // over NNODES * 10
    if (idx >= NNODES * 10) return;
    int r = idx / 10, q = idx % 10;
    float4 s = make_float4(0.f, 0.f, 0.f, 0.f);
    #pragma unroll
    for (int z = 0; z < 32; z++) {
        float4 v = *(const float4*)&g_tp[z][(size_t)r * NCP + q * 4];
        s.x += v.x; s.y += v.y; s.z += v.z; s.w += v.w;
    }
    *(float4*)&g_t[(size_t)r * NCLS + q * 4] = s;
}

// ---------------------------------------------------------------------------
// Layer-2 propagate + bias
// ---------------------------------------------------------------------------
__global__ void gather2_kernel(const float* __restrict__ b2, float* __restrict__ out) {
    int gw = (blockIdx.x * blockDim.x + threadIdx.x) >> 5;
    int lane = threadIdx.x & 31;
    if (gw >= NNODES) return;
    int i = gw;
    float di = g_dinv[i];
    float self = di * di;
    int c1 = lane + 32;
    float acc0 = 0.f, acc1 = 0.f;
    int beg = g_rowptr[i], end = g_rowptr[i + 1];
    for (int j = beg; j < end; j++) {
        int s = g_csr_src[j];
        float c = g_csr_coef[j];
        acc0 += c * g_t[(size_t)s * NCLS + lane];
        if (lane < 8) acc1 += c * g_t[(size_t)s * NCLS + c1];
    }
    out[(size_t)i * NCLS + lane] = acc0 + self * g_t[(size_t)i * NCLS + lane] + b2[lane];
    if (lane < 8)
        out[(size_t)i * NCLS + c1] = acc1 + self * g_t[(size_t)i * NCLS + c1] + b2[c1];
}

// ---------------------------------------------------------------------------
// Entry point
// ---------------------------------------------------------------------------
extern "C" void kernel_launch(void* const* d_in, const int* in_sizes, int n_in,
                              void* d_out, int out_size) {
    const float* x   = (const float*)d_in[0];
    const int*   ei  = (const int*)d_in[1];
    const float* W1  = (const float*)d_in[2];
    const float* b1  = (const float*)d_in[3];
    const float* W2  = (const float*)d_in[4];
    const float* b2  = (const float*)d_in[5];
    float*       out = (float*)d_out;

    const int* src = ei;
    const int* dst = ei + NEDGES;

    cudaFuncSetAttribute(gemm_fused_kernel,
                         cudaFuncAttributeMaxDynamicSharedMemorySize, GEMM1_SMEM);

    // Fused init (W2' + W1' prep + degree count; g_cnt enters zeroed)
    prep_init_kernel<<<PREP_TOTAL_BLOCKS, 256>>>(W1, W2, dst);
    scan_kernel<<<1, 1024>>>();
    fill_kernel<<<(NEDGES + 255) / 256, 256>>>(src, dst);

    // Layer 1 + fused layer-2 GEMM
    gather1_kernel<<<NNODES, 128>>>(x);
    {
        dim3 grid(DHID / BN, GA_ROWS / BM);   // (16, 79)
        gemm_fused_kernel<<<grid, 128, GEMM1_SMEM>>>(b1);
    }

    // Combine partials, then layer-2 propagate
    combine_kernel<<<(NNODES * 10 + 255) / 256, 256>>>();
    gather2_kernel<<<(NNODES * 32 + 127) / 128, 128>>>(b2, out);
}

// round 15
// speedup vs baseline: 1.0398x; 1.0398x over previous
#include <cuda_runtime.h>
#include <cuda_bf16.h>
#include <math.h>
#include <stdint.h>

// Problem constants (fixed by the reference)
#define NNODES 10000
#define NEDGES 320000
#define DIN    512
#define DHID   2048
#define NCLS   40

#define GA_ROWS 10112             // 79 * 128 (padded M; pad rows stay zero)

// GEMM1: A'[M x 1024]=[hi|lo], B'(W1^T)[2048 x 1536]=[hi|lo|hi], 24 K-chunks
#define KA1     1024
#define KB1     1536
#define BM      128
#define BN      128
#define BK      64                // 64 bf16 = 128 B per SMEM row
#define NKIT    24

#define KA2     4096              // W2' row width: [hi(2048) | lo(2048)]
#define NCP     48                // padded class count

// prep_init block ranges
#define PREP_W2_BLOCKS   NCP                          // 48
#define PREP_W1_BLOCKS   ((DIN / 32) * (DHID / 32))   // 1024
#define PREP_CNT_BLOCKS  ((NEDGES + 255) / 256)       // 1250
#define PREP_TOTAL_BLOCKS (PREP_W2_BLOCKS + PREP_W1_BLOCKS + PREP_CNT_BLOCKS)

// ---------------------------------------------------------------------------
// Device scratch (static globals: no runtime allocation allowed)
// g_cnt is zero at module load; scan_kernel re-zeroes it after use, so it is
// all-zero at the entry of EVERY kernel_launch call (incl. graph replays).
// ---------------------------------------------------------------------------
__device__ int   g_cnt[NNODES];
__device__ int   g_rowptr[NNODES + 1];
__device__ int   g_cursor[NNODES];
__device__ float g_dinv[NNODES];
__device__ int   g_csr_src[NEDGES];
__device__ float g_csr_coef[NEDGES];
__device__ __nv_bfloat16 g_Abf[(size_t)GA_ROWS * KA1];   // 20.7 MB
__device__ __nv_bfloat16 g_Bbf[(size_t)DHID * KB1];      // 6.3 MB
__device__ __nv_bfloat16 g_W2bf[(size_t)NCP * KA2];      // 393 KB
__device__ float g_tp[32][(size_t)NNODES * NCP];         // 61.4 MB partials
__device__ float g_t[(size_t)NNODES * NCLS];             // 1.6 MB

// ---------------------------------------------------------------------------
// PTX helpers
// ---------------------------------------------------------------------------
__device__ __forceinline__ uint32_t smem_u32(const void* p) {
    uint32_t a;
    asm("{ .reg .u64 t; cvta.to.shared.u64 t, %1; cvt.u32.u64 %0, t; }"
        : "=r"(a) : "l"(p));
    return a;
}
__device__ __forceinline__ void cp_async16(uint32_t saddr, const void* gaddr) {
    asm volatile("cp.async.cg.shared.global [%0], [%1], 16;"
                 :: "r"(saddr), "l"(gaddr) : "memory");
}
__device__ __forceinline__ void cp_commit() {
    asm volatile("cp.async.commit_group;" ::: "memory");
}
template <int N>
__device__ __forceinline__ void cp_wait() {
    asm volatile("cp.async.wait_group %0;" :: "n"(N) : "memory");
}
__device__ __forceinline__ void ldsm_x4(uint32_t addr, uint32_t& r0, uint32_t& r1,
                                        uint32_t& r2, uint32_t& r3) {
    asm volatile("ldmatrix.sync.aligned.m8n8.x4.shared.b16 {%0,%1,%2,%3}, [%4];"
                 : "=r"(r0), "=r"(r1), "=r"(r2), "=r"(r3) : "r"(addr));
}
__device__ __forceinline__ void mma_bf16(float* d, const uint32_t* a, const uint32_t* b) {
    asm volatile(
        "mma.sync.aligned.m16n8k16.row.col.f32.bf16.bf16.f32 "
        "{%0,%1,%2,%3}, {%4,%5,%6,%7}, {%8,%9}, {%0,%1,%2,%3};"
        : "+f"(d[0]), "+f"(d[1]), "+f"(d[2]), "+f"(d[3])
        : "r"(a[0]), "r"(a[1]), "r"(a[2]), "r"(a[3]), "r"(b[0]), "r"(b[1]));
}
__device__ __forceinline__ void stcs_f2(void* p, float a, float b) {
    asm volatile("st.global.cs.v2.f32 [%0], {%1, %2};"
                 :: "l"(p), "f"(a), "f"(b) : "memory");
}
// pack two fp32 -> bf16x2 (v0 in low half), and produce the lo-residual pack
__device__ __forceinline__ uint32_t pack_split(float v0, float v1, uint32_t& loOut) {
    uint32_t hi;
    asm("cvt.rn.bf16x2.f32 %0, %1, %2;" : "=r"(hi) : "f"(v1), "f"(v0));
    float h0 = __uint_as_float(hi << 16);
    float h1 = __uint_as_float(hi & 0xffff0000u);
    float l0 = v0 - h0, l1 = v1 - h1;
    asm("cvt.rn.bf16x2.f32 %0, %1, %2;" : "=r"(loOut) : "f"(l1), "f"(l0));
    return hi;
}

// ---------------------------------------------------------------------------
// Fused init + count:
//   blocks [0, 48):        W2' rows (hi|lo)
//   blocks [48, 1072):     W1 transpose+split tiles (16 x 64 tiles of 32x32)
//   blocks [1072, 2322):   degree histogram (g_cnt pre-zeroed — see above)
// ---------------------------------------------------------------------------
__global__ void prep_init_kernel(const float* __restrict__ W1,
                                 const float* __restrict__ W2,
                                 const int* __restrict__ dst) {
    __shared__ float tile[32][33];
    int b = blockIdx.x;
    int tid = threadIdx.x;
    if (b < PREP_W2_BLOCKS) {
        int n = b;
        __nv_bfloat16* row = &g_W2bf[(size_t)n * KA2];
        for (int k = tid; k < DHID; k += blockDim.x) {
            float w = (n < NCLS) ? W2[(size_t)k * NCLS + n] : 0.0f;
            __nv_bfloat16 hi = __float2bfloat16(w);
            __nv_bfloat16 lo = __float2bfloat16(w - __bfloat162float(hi));
            row[k]        = hi;
            row[2048 + k] = lo;
        }
    } else if (b < PREP_W2_BLOCKS + PREP_W1_BLOCKS) {
        int tb = b - PREP_W2_BLOCKS;               // 0..1023
        int k0 = (tb & 15) * 32;                   // DIN/32 = 16
        int n0 = (tb >> 4) * 32;                   // DHID/32 = 64
        int tx = tid & 31, ty = tid >> 5;          // (32, 8)
        #pragma unroll
        for (int j = 0; j < 4; j++)
            tile[ty + 8 * j][tx] = W1[(size_t)(k0 + ty + 8 * j) * DHID + n0 + tx];
        __syncthreads();
        #pragma unroll
        for (int j = 0; j < 4; j++) {
            int n = n0 + ty + 8 * j;
            int k = k0 + tx;
            float w = tile[tx][ty + 8 * j];
            __nv_bfloat16 hi = __float2bfloat16(w);
            __nv_bfloat16 lo = __float2bfloat16(w - __bfloat162float(hi));
            __nv_bfloat16* row = &g_Bbf[(size_t)n * KB1];
            row[k]        = hi;
            row[512 + k]  = lo;
            row[1024 + k] = hi;
        }
    } else {
        int e = (b - PREP_W2_BLOCKS - PREP_W1_BLOCKS) * 256 + tid;
        if (e < NEDGES) atomicAdd(&g_cnt[dst[e]], 1);
    }
}

// Single-block warp-shuffle scan + dinv + cursor.
// Re-zeroes g_cnt after consuming it (keeps the entry invariant for the
// count blocks of prep_init_kernel on the next call / graph replay).
__global__ void scan_kernel() {
    __shared__ int warp_sums[32];
    __shared__ int s_carry;
    int tid = threadIdx.x, lane = tid & 31, w = tid >> 5;
    if (tid == 0) { s_carry = 0; g_rowptr[0] = 0; }
    __syncthreads();
    for (int base = 0; base < NNODES; base += 1024) {
        int i = base + tid;
        int v = (i < NNODES) ? g_cnt[i] : 0;
        if (i < NNODES) g_cnt[i] = 0;     // recycle for next run
        int x = v;
        #pragma unroll
        for (int off = 1; off < 32; off <<= 1) {
            int t = __shfl_up_sync(0xFFFFFFFFu, x, off);
            if (lane >= off) x += t;
        }
        if (lane == 31) warp_sums[w] = x;
        __syncthreads();
        if (w == 0) {
            int s = warp_sums[lane];
            #pragma unroll
            for (int off = 1; off < 32; off <<= 1) {
                int t = __shfl_up_sync(0xFFFFFFFFu, s, off);
                if (lane >= off) s += t;
            }
            warp_sums[lane] = s;
        }
        __syncthreads();
        int warp_off = (w > 0) ? warp_sums[w - 1] : 0;
        int incl = x + warp_off + s_carry;
        if (i < NNODES) {
            g_rowptr[i + 1] = incl;
            g_cursor[i]     = incl - v;
            g_dinv[i]       = rsqrtf((float)v + 1.0f);
        }
        __syncthreads();
        if (tid == 0) s_carry += warp_sums[31];
        __syncthreads();
    }
}

__global__ void fill_kernel(const int* __restrict__ src, const int* __restrict__ dst) {
    int e = blockIdx.x * blockDim.x + threadIdx.x;
    if (e >= NEDGES) return;
    int s = src[e], d = dst[e];
    int p = atomicAdd(&g_cursor[d], 1);
    g_csr_src[p]  = s;
    g_csr_coef[p] = g_dinv[s] * g_dinv[d];
}

// ---------------------------------------------------------------------------
// Layer-1 propagate + split pack: A'[i] = [hi | lo]  (R13 version — fastest)
// ---------------------------------------------------------------------------
__global__ void gather1_kernel(const float* __restrict__ x) {
    int i = blockIdx.x;
    int f4 = threadIdx.x;
    float di = g_dinv[i];
    float self = di * di;
    float4 xv = ((const float4*)&x[(size_t)i * DIN])[f4];
    float4 acc;
    acc.x = self * xv.x; acc.y = self * xv.y;
    acc.z = self * xv.z; acc.w = self * xv.w;
    int beg = g_rowptr[i], end = g_rowptr[i + 1];
    int j = beg;
    for (; j + 1 < end; j += 2) {
        int s0 = g_csr_src[j],     s1 = g_csr_src[j + 1];
        float c0 = g_csr_coef[j],  c1 = g_csr_coef[j + 1];
        float4 v0 = ((const float4*)&x[(size_t)s0 * DIN])[f4];
        float4 v1 = ((const float4*)&x[(size_t)s1 * DIN])[f4];
        acc.x += c0 * v0.x + c1 * v1.x;
        acc.y += c0 * v0.y + c1 * v1.y;
        acc.z += c0 * v0.z + c1 * v1.z;
        acc.w += c0 * v0.w + c1 * v1.w;
    }
    if (j < end) {
        int s = g_csr_src[j];
        float c = g_csr_coef[j];
        float4 v = ((const float4*)&x[(size_t)s * DIN])[f4];
        acc.x += c * v.x; acc.y += c * v.y;
        acc.z += c * v.z; acc.w += c * v.w;
    }
    float a[4] = {acc.x, acc.y, acc.z, acc.w};
    union { __nv_bfloat16 h[4]; uint2 u; } hp, lp;
    #pragma unroll
    for (int t = 0; t < 4; t++) {
        hp.h[t] = __float2bfloat16(a[t]);
        lp.h[t] = __float2bfloat16(a[t] - __bfloat162float(hp.h[t]));
    }
    int k = f4 * 4;
    __nv_bfloat16* row = &g_Abf[(size_t)i * KA1];
    *(uint2*)&row[k]       = hp.u;
    *(uint2*)&row[512 + k] = lp.u;
}

// ---------------------------------------------------------------------------
// Fused GEMM1+GEMM2 (mma.sync bf16):
//   h_block = relu(A' @ B'^T + b1)   (fp32 in registers, never materialized)
//   partial[c] = h_block @ W2_slice  (3-term split, A-frags built from C-frags)
// 128x128x64 CTA tile, 128 threads (4 warps, 2x2, warp tile 64x64), 3-stage
// pipeline, occ 2. The 24 KB W2 slice is prefetched into stage buffer 0 at
// kt = NKIT-2 (buffer 0's last chunk, 21, computed at kt=21 and freed by the
// barrier at kt=22), overlapping the epilogue's W2 load with the last two
// chunks of MMA compute. Each warp writes a [64 x 48] fp32 partial into slice
// (blockIdx.x*2 + warp_n); combine_kernel sums the 32 slices.
// ---------------------------------------------------------------------------
#define STAGE_BYTES (BM * BK * 2 + BN * BK * 2)   // 32768
#define GEMM1_SMEM  (3 * STAGE_BYTES)             // 98304

__global__ __launch_bounds__(128, 2)
void gemm_fused_kernel(const float* __restrict__ bias) {
    extern __shared__ char dsm[];
    const uint32_t sbase = smem_u32(dsm);
    const int tid  = threadIdx.x;
    const int wid  = tid >> 5;
    const int lane = tid & 31;
    const int warp_m = wid & 1;
    const int warp_n = wid >> 1;
    const int block_n = blockIdx.x * BN;
    const int block_m = blockIdx.y * BM;

    uint32_t sA[3], sB[3];
    #pragma unroll
    for (int s = 0; s < 3; s++) {
        sA[s] = sbase + s * STAGE_BYTES;
        sB[s] = sA[s] + (uint32_t)(BM * BK * 2);
    }

    auto load_stage = [&](int kt, int s) {
        const int ka = ((kt < 8) ? kt : kt - 8) * BK;
        const int kb = kt * BK;
        #pragma unroll
        for (int i = 0; i < 8; i++) {
            int t = tid + i * 128;
            int row = t >> 3, c = t & 7;
            uint32_t sw = (uint32_t)(row << 7) + (uint32_t)(((c ^ (row & 7)) << 4));
            cp_async16(sA[s] + sw, &g_Abf[(size_t)(block_m + row) * KA1 + ka + c * 8]);
        }
        #pragma unroll
        for (int i = 0; i < 8; i++) {
            int t = tid + i * 128;
            int row = t >> 3, c = t & 7;
            uint32_t sw = (uint32_t)(row << 7) + (uint32_t)(((c ^ (row & 7)) << 4));
            cp_async16(sB[s] + sw, &g_Bbf[(size_t)(block_n + row) * KB1 + kb + c * 8]);
        }
        cp_commit();
    };

    // W2 slice [48 x 128] hi + lo -> buffer 0 (24 KB), 256-B rows,
    // 16-chunk swizzle: sw = (c&8) | ((c ^ (row&7)) & 7).
    auto load_w2 = [&]() {
        #pragma unroll
        for (int i = 0; i < 12; i++) {
            int t = tid + i * 128;                 // 0..1535
            int blk = (t >= 768) ? 1 : 0;
            int q = t - blk * 768;
            int row = q >> 4, c = q & 15;
            uint32_t sw = (uint32_t)((c & 8) | ((c ^ (row & 7)) & 7));
            cp_async16(sbase + (uint32_t)(blk * 12288 + row * 256) + (sw << 4),
                       &g_W2bf[(size_t)row * KA2 + blk * 2048 + block_n + c * 8]);
        }
        cp_commit();
    };

    const int grp  = lane >> 3;
    const int lrow = lane & 7;
    const int arow_base = warp_m * 64 + ((grp & 1) << 3) + lrow;
    const int akc_half = grp >> 1;
    const int brow_base = warp_n * 64 + ((grp >> 1) << 3) + lrow;
    const int bkc_half = grp & 1;

    float acc[4][8][4];
    #pragma unroll
    for (int i = 0; i < 4; i++)
        #pragma unroll
        for (int j = 0; j < 8; j++)
            #pragma unroll
            for (int q = 0; q < 4; q++) acc[i][j][q] = 0.0f;

    load_stage(0, 0);
    load_stage(1, 1);

    for (int kt = 0; kt < NKIT; kt++) {
        const int cur = kt % 3;
        // wait<1>: all groups except the newest are done. At kt=NKIT-1 the
        // newest group is the W2 slice, so chunk NKIT-1 is guaranteed ready.
        cp_wait<1>();
        __syncthreads();
        if (kt + 2 < NKIT)       load_stage(kt + 2, (kt + 2) % 3);
        else if (kt + 2 == NKIT) load_w2();   // buffer 0 is free from here

        #pragma unroll
        for (int ks = 0; ks < 4; ks++) {
            uint32_t a[4][4];
            const int kca = 2 * ks + akc_half;
            #pragma unroll
            for (int mt = 0; mt < 4; mt++) {
                const int arow = arow_base + mt * 16;
                ldsm_x4(sA[cur] + (uint32_t)(arow << 7) + (uint32_t)(((kca ^ (arow & 7)) << 4)),
                        a[mt][0], a[mt][1], a[mt][2], a[mt][3]);
            }
            const int kcb = 2 * ks + bkc_half;
            uint32_t b[4][4];
            #pragma unroll
            for (int p = 0; p < 4; p++) {
                const int brow = brow_base + p * 16;
                ldsm_x4(sB[cur] + (uint32_t)(brow << 7) + (uint32_t)(((kcb ^ (brow & 7)) << 4)),
                        b[p][0], b[p][1], b[p][2], b[p][3]);
            }
            #pragma unroll
            for (int mt = 0; mt < 4; mt++)
                #pragma unroll
                for (int p = 0; p < 4; p++) {
                    mma_bf16(acc[mt][2 * p + 0], a[mt], &b[p][0]);
                    mma_bf16(acc[mt][2 * p + 1], a[mt], &b[p][2]);
                }
        }
    }

    // ------- Fused epilogue: partial = relu(acc+b1) @ W2_slice -------
    cp_wait<0>();       // W2 slice complete (likely already done)
    __syncthreads();    // publish to all threads
    const uint32_t sW = sbase;

    const int grpID = lane >> 2;
    const int tg    = lane & 3;
    const int brow_lane = ((grp >> 1) << 3) + lrow;   // 0..15
    float* dst = g_tp[blockIdx.x * 2 + warp_n];

    #pragma unroll
    for (int mt = 0; mt < 4; mt++) {
        float t2[6][4];
        #pragma unroll
        for (int t = 0; t < 6; t++)
            #pragma unroll
            for (int q = 0; q < 4; q++) t2[t][q] = 0.0f;

        #pragma unroll
        for (int j = 0; j < 4; j++) {
            int colA = block_n + warp_n * 64 + 16 * j + tg * 2;
            float b00 = bias[colA],     b01 = bias[colA + 1];
            float b10 = bias[colA + 8], b11 = bias[colA + 9];
            float v00 = fmaxf(acc[mt][2 * j][0] + b00, 0.f);
            float v01 = fmaxf(acc[mt][2 * j][1] + b01, 0.f);
            float v02 = fmaxf(acc[mt][2 * j][2] + b00, 0.f);
            float v03 = fmaxf(acc[mt][2 * j][3] + b01, 0.f);
            float v10 = fmaxf(acc[mt][2 * j + 1][0] + b10, 0.f);
            float v11 = fmaxf(acc[mt][2 * j + 1][1] + b11, 0.f);
            float v12 = fmaxf(acc[mt][2 * j + 1][2] + b10, 0.f);
            float v13 = fmaxf(acc[mt][2 * j + 1][3] + b11, 0.f);

            uint32_t aHi[4], aLo[4];
            aHi[0] = pack_split(v00, v01, aLo[0]);
            aHi[1] = pack_split(v02, v03, aLo[1]);
            aHi[2] = pack_split(v10, v11, aLo[2]);
            aHi[3] = pack_split(v12, v13, aLo[3]);

            const int cfull = warp_n * 8 + 2 * j + bkc_half;   // 16B-chunk 0..15
            uint32_t bHi[3][4], bLo[3][4];
            #pragma unroll
            for (int p = 0; p < 3; p++) {
                const int brow = brow_lane + p * 16;
                uint32_t sw = (uint32_t)((cfull & 8) | ((cfull ^ (brow & 7)) & 7));
                uint32_t off = (uint32_t)(brow * 256) + (sw << 4);
                ldsm_x4(sW + off,         bHi[p][0], bHi[p][1], bHi[p][2], bHi[p][3]);
                ldsm_x4(sW + 12288 + off, bLo[p][0], bLo[p][1], bLo[p][2], bLo[p][3]);
            }
            #pragma unroll
            for (int p = 0; p < 3; p++) {
                mma_bf16(t2[2 * p + 0], aHi, &bHi[p][0]);
                mma_bf16(t2[2 * p + 1], aHi, &bHi[p][2]);
                mma_bf16(t2[2 * p + 0], aHi, &bLo[p][0]);
                mma_bf16(t2[2 * p + 1], aHi, &bLo[p][2]);
                mma_bf16(t2[2 * p + 0], aLo, &bHi[p][0]);
                mma_bf16(t2[2 * p + 1], aLo, &bHi[p][2]);
            }
        }

        const int r0 = block_m + warp_m * 64 + mt * 16 + grpID;
        const int r1 = r0 + 8;
        #pragma unroll
        for (int t = 0; t < 6; t++) {
            const int col = t * 8 + tg * 2;
            if (r0 < NNODES) stcs_f2(&dst[(size_t)r0 * NCP + col], t2[t][0], t2[t][1]);
            if (r1 < NNODES) stcs_f2(&dst[(size_t)r1 * NCP + col], t2[t][2], t2[t][3]);
        }
    }
}

// combine the 32 partial slices: g_t[r, 0..39] = sum_z g_tp[z][r, 0..39]
__global__ void combine_kernel() {
    int idx = blockIdx.x * blockDim.x + threadIdx.x;   // over NNODES * 10
    if (idx >= NNODES * 10) return;
    int r = idx / 10, q = idx % 10;
    float4 s = make_float4(0.f, 0.f, 0.f, 0.f);
    #pragma unroll
    for (int z = 0; z < 32; z++) {
        float4 v = *(const float4*)&g_tp[z][(size_t)r * NCP + q * 4];
        s.x += v.x; s.y += v.y; s.z += v.z; s.w += v.w;
    }
    *(float4*)&g_t[(size_t)r * NCLS + q * 4] = s;
}

// ---------------------------------------------------------------------------
// Layer-2 propagate + bias
// ---------------------------------------------------------------------------
__global__ void gather2_kernel(const float* __restrict__ b2, float* __restrict__ out) {
    int gw = (blockIdx.x * blockDim.x + threadIdx.x) >> 5;
    int lane = threadIdx.x & 31;
    if (gw >= NNODES) return;
    int i = gw;
    float di = g_dinv[i];
    float self = di * di;
    int c1 = lane + 32;
    float acc0 = 0.f, acc1 = 0.f;
    int beg = g_rowptr[i], end = g_rowptr[i + 1];
    for (int j = beg; j < end; j++) {
        int s = g_csr_src[j];
        float c = g_csr_coef[j];
        acc0 += c * g_t[(size_t)s * NCLS + lane];
        if (lane < 8) acc1 += c * g_t[(size_t)s * NCLS + c1];
    }
    out[(size_t)i * NCLS + lane] = acc0 + self * g_t[(size_t)i * NCLS + lane] + b2[lane];
    if (lane < 8)
        out[(size_t)i * NCLS + c1] = acc1 + self * g_t[(size_t)i * NCLS + c1] + b2[c1];
}

// ---------------------------------------------------------------------------
// Entry point
// ---------------------------------------------------------------------------
extern "C" void kernel_launch(void* const* d_in, const int* in_sizes, int n_in,
                              void* d_out, int out_size) {
    const float* x   = (const float*)d_in[0];
    const int*   ei  = (const int*)d_in[1];
    const float* W1  = (const float*)d_in[2];
    const float* b1  = (const float*)d_in[3];
    const float* W2  = (const float*)d_in[4];
    const float* b2  = (const float*)d_in[5];
    float*       out = (float*)d_out;

    const int* src = ei;
    const int* dst = ei + NEDGES;

    cudaFuncSetAttribute(gemm_fused_kernel,
                         cudaFuncAttributeMaxDynamicSharedMemorySize, GEMM1_SMEM);

    // Fused init (W2' + W1' prep + degree count; g_cnt enters zeroed)
    prep_init_kernel<<<PREP_TOTAL_BLOCKS, 256>>>(W1, W2, dst);
    scan_kernel<<<1, 1024>>>();
    fill_kernel<<<(NEDGES + 255) / 256, 256>>>(src, dst);

    // Layer 1 + fused layer-2 GEMM
    gather1_kernel<<<NNODES, 128>>>(x);
    {
        dim3 grid(DHID / BN, GA_ROWS / BM);   // (16, 79)
        gemm_fused_kernel<<<grid, 128, GEMM1_SMEM>>>(b1);
    }

    // Combine partials, then layer-2 propagate
    combine_kernel<<<(NNODES * 10 + 255) / 256, 256>>>();
    gather2_kernel<<<(NNODES * 32 + 127) / 128, 128>>>(b2, out);
}

// round 16
// speedup vs baseline: 1.0760x; 1.0348x over previous
#include <cuda_runtime.h>
#include <cuda_bf16.h>
#include <math.h>
#include <stdint.h>

// Problem constants (fixed by the reference)
#define NNODES 10000
#define NEDGES 320000
#define DIN    512
#define DHID   2048
#define NCLS   40

#define GA_ROWS 10112             // 79 * 128 (padded M; pad rows stay zero)

// GEMM1: A'[M x 1024]=[hi|lo], B'(W1^T)[2048 x 1024]=[hi|lo]
// 16 superstages: ss<8 -> (A_hi[g] x B_hi[g]) + (A_hi[g] x B_lo[g])
//                 ss>=8 -> (A_lo[g] x B_hi[g])
#define KA1     1024
#define KB1     1024
#define BM      128
#define BN      128
#define BK      64                // 64 bf16 = 128 B per SMEM row
#define NSS     16

#define KA2     4096              // W2' row width: [hi(2048) | lo(2048)]
#define NCP     48                // padded class count

// prep_init block ranges
#define PREP_W2_BLOCKS   NCP                          // 48
#define PREP_W1_BLOCKS   ((DIN / 32) * (DHID / 32))   // 1024
#define PREP_CNT_BLOCKS  ((NEDGES + 255) / 256)       // 1250
#define PREP_TOTAL_BLOCKS (PREP_W2_BLOCKS + PREP_W1_BLOCKS + PREP_CNT_BLOCKS)

// ---------------------------------------------------------------------------
// Device scratch (static globals: no runtime allocation allowed)
// g_cnt is zero at module load; scan_kernel re-zeroes it after use, so it is
// all-zero at the entry of EVERY kernel_launch call (incl. graph replays).
// ---------------------------------------------------------------------------
__device__ int   g_cnt[NNODES];
__device__ int   g_rowptr[NNODES + 1];
__device__ int   g_cursor[NNODES];
__device__ float g_dinv[NNODES];
__device__ int   g_csr_src[NEDGES];
__device__ float g_csr_coef[NEDGES];
__device__ __nv_bfloat16 g_Abf[(size_t)GA_ROWS * KA1];   // 20.7 MB
__device__ __nv_bfloat16 g_Bbf[(size_t)DHID * KB1];      // 4.2 MB
__device__ __nv_bfloat16 g_W2bf[(size_t)NCP * KA2];      // 393 KB
__device__ float g_tp[32][(size_t)NNODES * NCP];         // 61.4 MB partials
__device__ float g_t[(size_t)NNODES * NCLS];             // 1.6 MB

// ---------------------------------------------------------------------------
// PTX helpers
// ---------------------------------------------------------------------------
__device__ __forceinline__ uint32_t smem_u32(const void* p) {
    uint32_t a;
    asm("{ .reg .u64 t; cvta.to.shared.u64 t, %1; cvt.u32.u64 %0, t; }"
        : "=r"(a) : "l"(p));
    return a;
}
__device__ __forceinline__ void cp_async16(uint32_t saddr, const void* gaddr) {
    asm volatile("cp.async.cg.shared.global [%0], [%1], 16;"
                 :: "r"(saddr), "l"(gaddr) : "memory");
}
__device__ __forceinline__ void cp_commit() {
    asm volatile("cp.async.commit_group;" ::: "memory");
}
template <int N>
__device__ __forceinline__ void cp_wait() {
    asm volatile("cp.async.wait_group %0;" :: "n"(N) : "memory");
}
__device__ __forceinline__ void ldsm_x4(uint32_t addr, uint32_t& r0, uint32_t& r1,
                                        uint32_t& r2, uint32_t& r3) {
    asm volatile("ldmatrix.sync.aligned.m8n8.x4.shared.b16 {%0,%1,%2,%3}, [%4];"
                 : "=r"(r0), "=r"(r1), "=r"(r2), "=r"(r3) : "r"(addr));
}
__device__ __forceinline__ void mma_bf16(float* d, const uint32_t* a, const uint32_t* b) {
    asm volatile(
        "mma.sync.aligned.m16n8k16.row.col.f32.bf16.bf16.f32 "
        "{%0,%1,%2,%3}, {%4,%5,%6,%7}, {%8,%9}, {%0,%1,%2,%3};"
        : "+f"(d[0]), "+f"(d[1]), "+f"(d[2]), "+f"(d[3])
        : "r"(a[0]), "r"(a[1]), "r"(a[2]), "r"(a[3]), "r"(b[0]), "r"(b[1]));
}
__device__ __forceinline__ void stcs_f2(void* p, float a, float b) {
    asm volatile("st.global.cs.v2.f32 [%0], {%1, %2};"
                 :: "l"(p), "f"(a), "f"(b) : "memory");
}
// pack two fp32 -> bf16x2 (v0 in low half), and produce the lo-residual pack
__device__ __forceinline__ uint32_t pack_split(float v0, float v1, uint32_t& loOut) {
    uint32_t hi;
    asm("cvt.rn.bf16x2.f32 %0, %1, %2;" : "=r"(hi) : "f"(v1), "f"(v0));
    float h0 = __uint_as_float(hi << 16);
    float h1 = __uint_as_float(hi & 0xffff0000u);
    float l0 = v0 - h0, l1 = v1 - h1;
    asm("cvt.rn.bf16x2.f32 %0, %1, %2;" : "=r"(loOut) : "f"(l1), "f"(l0));
    return hi;
}

// ---------------------------------------------------------------------------
// Fused init + count:
//   blocks [0, 48):        W2' rows (hi|lo)
//   blocks [48, 1072):     W1 transpose+split tiles (16 x 64 tiles of 32x32)
//   blocks [1072, 2322):   degree histogram (g_cnt pre-zeroed — see above)
// ---------------------------------------------------------------------------
__global__ void prep_init_kernel(const float* __restrict__ W1,
                                 const float* __restrict__ W2,
                                 const int* __restrict__ dst) {
    __shared__ float tile[32][33];
    int b = blockIdx.x;
    int tid = threadIdx.x;
    if (b < PREP_W2_BLOCKS) {
        int n = b;
        __nv_bfloat16* row = &g_W2bf[(size_t)n * KA2];
        for (int k = tid; k < DHID; k += blockDim.x) {
            float w = (n < NCLS) ? W2[(size_t)k * NCLS + n] : 0.0f;
            __nv_bfloat16 hi = __float2bfloat16(w);
            __nv_bfloat16 lo = __float2bfloat16(w - __bfloat162float(hi));
            row[k]        = hi;
            row[2048 + k] = lo;
        }
    } else if (b < PREP_W2_BLOCKS + PREP_W1_BLOCKS) {
        int tb = b - PREP_W2_BLOCKS;               // 0..1023
        int k0 = (tb & 15) * 32;                   // DIN/32 = 16
        int n0 = (tb >> 4) * 32;                   // DHID/32 = 64
        int tx = tid & 31, ty = tid >> 5;          // (32, 8)
        #pragma unroll
        for (int j = 0; j < 4; j++)
            tile[ty + 8 * j][tx] = W1[(size_t)(k0 + ty + 8 * j) * DHID + n0 + tx];
        __syncthreads();
        #pragma unroll
        for (int j = 0; j < 4; j++) {
            int n = n0 + ty + 8 * j;
            int k = k0 + tx;
            float w = tile[tx][ty + 8 * j];
            __nv_bfloat16 hi = __float2bfloat16(w);
            __nv_bfloat16 lo = __float2bfloat16(w - __bfloat162float(hi));
            __nv_bfloat16* row = &g_Bbf[(size_t)n * KB1];
            row[k]       = hi;
            row[512 + k] = lo;
        }
    } else {
        int e = (b - PREP_W2_BLOCKS - PREP_W1_BLOCKS) * 256 + tid;
        if (e < NEDGES) atomicAdd(&g_cnt[dst[e]], 1);
    }
}

// Single-block warp-shuffle scan + dinv + cursor.
// Re-zeroes g_cnt after consuming it (keeps the entry invariant for the
// count blocks of prep_init_kernel on the next call / graph replay).
__global__ void scan_kernel() {
    __shared__ int warp_sums[32];
    __shared__ int s_carry;
    int tid = threadIdx.x, lane = tid & 31, w = tid >> 5;
    if (tid == 0) { s_carry = 0; g_rowptr[0] = 0; }
    __syncthreads();
    for (int base = 0; base < NNODES; base += 1024) {
        int i = base + tid;
        int v = (i < NNODES) ? g_cnt[i] : 0;
        if (i < NNODES) g_cnt[i] = 0;     // recycle for next run
        int x = v;
        #pragma unroll
        for (int off = 1; off < 32; off <<= 1) {
            int t = __shfl_up_sync(0xFFFFFFFFu, x, off);
            if (lane >= off) x += t;
        }
        if (lane == 31) warp_sums[w] = x;
        __syncthreads();
        if (w == 0) {
            int s = warp_sums[lane];
            #pragma unroll
            for (int off = 1; off < 32; off <<= 1) {
                int t = __shfl_up_sync(0xFFFFFFFFu, s, off);
                if (lane >= off) s += t;
            }
            warp_sums[lane] = s;
        }
        __syncthreads();
        int warp_off = (w > 0) ? warp_sums[w - 1] : 0;
        int incl = x + warp_off + s_carry;
        if (i < NNODES) {
            g_rowptr[i + 1] = incl;
            g_cursor[i]     = incl - v;
            g_dinv[i]       = rsqrtf((float)v + 1.0f);
        }
        __syncthreads();
        if (tid == 0) s_carry += warp_sums[31];
        __syncthreads();
    }
}

__global__ void fill_kernel(const int* __restrict__ src, const int* __restrict__ dst) {
    int e = blockIdx.x * blockDim.x + threadIdx.x;
    if (e >= NEDGES) return;
    int s = src[e], d = dst[e];
    int p = atomicAdd(&g_cursor[d], 1);
    g_csr_src[p]  = s;
    g_csr_coef[p] = g_dinv[s] * g_dinv[d];
}

// ---------------------------------------------------------------------------
// Layer-1 propagate + split pack: A'[i] = [hi | lo]
// ---------------------------------------------------------------------------
__global__ void gather1_kernel(const float* __restrict__ x) {
    int i = blockIdx.x;
    int f4 = threadIdx.x;
    float di = g_dinv[i];
    float self = di * di;
    float4 xv = ((const float4*)&x[(size_t)i * DIN])[f4];
    float4 acc;
    acc.x = self * xv.x; acc.y = self * xv.y;
    acc.z = self * xv.z; acc.w = self * xv.w;
    int beg = g_rowptr[i], end = g_rowptr[i + 1];
    int j = beg;
    for (; j + 1 < end; j += 2) {
        int s0 = g_csr_src[j],     s1 = g_csr_src[j + 1];
        float c0 = g_csr_coef[j],  c1 = g_csr_coef[j + 1];
        float4 v0 = ((const float4*)&x[(size_t)s0 * DIN])[f4];
        float4 v1 = ((const float4*)&x[(size_t)s1 * DIN])[f4];
        acc.x += c0 * v0.x + c1 * v1.x;
        acc.y += c0 * v0.y + c1 * v1.y;
        acc.z += c0 * v0.z + c1 * v1.z;
        acc.w += c0 * v0.w + c1 * v1.w;
    }
    if (j < end) {
        int s = g_csr_src[j];
        float c = g_csr_coef[j];
        float4 v = ((const float4*)&x[(size_t)s * DIN])[f4];
        acc.x += c * v.x; acc.y += c * v.y;
        acc.z += c * v.z; acc.w += c * v.w;
    }
    float a[4] = {acc.x, acc.y, acc.z, acc.w};
    union { __nv_bfloat16 h[4]; uint2 u; } hp, lp;
    #pragma unroll
    for (int t = 0; t < 4; t++) {
        hp.h[t] = __float2bfloat16(a[t]);
        lp.h[t] = __float2bfloat16(a[t] - __bfloat162float(hp.h[t]));
    }
    int k = f4 * 4;
    __nv_bfloat16* row = &g_Abf[(size_t)i * KA1];
    *(uint2*)&row[k]       = hp.u;
    *(uint2*)&row[512 + k] = lp.u;
}

// ---------------------------------------------------------------------------
// Fused GEMM1+GEMM2 (mma.sync bf16), superstage K-loop:
//   ss in [0,8):  load {A_hi[g], B_hi[g], B_lo[g]} (48 KB); compute 2 chunks
//   ss in [8,16): load {A_lo[g], B_hi[g]}          (32 KB); compute 1 chunk
// Two 48 KB buffers (96 KB total, occ 2). A_hi and B_hi are each fetched once
// (was twice) -> L2 tile traffic -17%. W2 slice prefetched into buffer 0 at
// the last superstage. Epilogue: partial = relu(acc+b1) @ W2_slice into slice
// (blockIdx.x*2 + warp_n); combine_kernel sums the 32 slices.
// ---------------------------------------------------------------------------
#define SS_BYTES   49152                  // 3 x 16 KB slots
#define GEMM1_SMEM (2 * SS_BYTES)         // 98304

__global__ __launch_bounds__(128, 2)
void gemm_fused_kernel(const float* __restrict__ bias) {
    extern __shared__ char dsm[];
    const uint32_t sbase = smem_u32(dsm);
    const int tid  = threadIdx.x;
    const int wid  = tid >> 5;
    const int lane = tid & 31;
    const int warp_m = wid & 1;
    const int warp_n = wid >> 1;
    const int block_n = blockIdx.x * BN;
    const int block_m = blockIdx.y * BM;

    uint32_t buf[2] = { sbase, sbase + SS_BYTES };

    // load a 128x64 bf16 chunk (16 KB) from a [*, 1024]-stride matrix
    auto load_chunk = [&](uint32_t sdst, const __nv_bfloat16* gsrc,
                          int grow0, int kofs) {
        #pragma unroll
        for (int i = 0; i < 8; i++) {
            int t = tid + i * 128;
            int row = t >> 3, c = t & 7;
            uint32_t sw = (uint32_t)(row << 7) + (uint32_t)(((c ^ (row & 7)) << 4));
            cp_async16(sdst + sw, &gsrc[(size_t)(grow0 + row) * 1024 + kofs + c * 8]);
        }
    };

    auto load_ss = [&](int ss, int bsel) {
        uint32_t B = buf[bsel];
        if (ss < 8) {
            int g = ss;
            load_chunk(B,          g_Abf, block_m, g * BK);          // A_hi[g]
            load_chunk(B + 16384,  g_Bbf, block_n, g * BK);          // B_hi[g]
            load_chunk(B + 32768,  g_Bbf, block_n, (8 + g) * BK);    // B_lo[g]
        } else {
            int g = ss - 8;
            load_chunk(B,          g_Abf, block_m, (8 + g) * BK);    // A_lo[g]
            load_chunk(B + 16384,  g_Bbf, block_n, g * BK);          // B_hi[g]
        }
        cp_commit();
    };

    auto load_w2 = [&]() {
        #pragma unroll
        for (int i = 0; i < 12; i++) {
            int t = tid + i * 128;                 // 0..1535
            int blk = (t >= 768) ? 1 : 0;
            int q = t - blk * 768;
            int row = q >> 4, c = q & 15;
            uint32_t sw = (uint32_t)((c & 8) | ((c ^ (row & 7)) & 7));
            cp_async16(buf[0] + (uint32_t)(blk * 12288 + row * 256) + (sw << 4),
                       &g_W2bf[(size_t)row * KA2 + blk * 2048 + block_n + c * 8]);
        }
        cp_commit();
    };

    const int grp  = lane >> 3;
    const int lrow = lane & 7;
    const int arow_base = warp_m * 64 + ((grp & 1) << 3) + lrow;
    const int akc_half = grp >> 1;
    const int brow_base = warp_n * 64 + ((grp >> 1) << 3) + lrow;
    const int bkc_half = grp & 1;

    float acc[4][8][4];
    #pragma unroll
    for (int i = 0; i < 4; i++)
        #pragma unroll
        for (int j = 0; j < 8; j++)
            #pragma unroll
            for (int q = 0; q < 4; q++) acc[i][j][q] = 0.0f;

    // one 64-K chunk of MMA from slots aAddr/bAddr
    auto compute_chunk = [&](uint32_t aAddr, uint32_t bAddr) {
        #pragma unroll
        for (int ks = 0; ks < 4; ks++) {
            uint32_t a[4][4];
            const int kca = 2 * ks + akc_half;
            #pragma unroll
            for (int mt = 0; mt < 4; mt++) {
                const int arow = arow_base + mt * 16;
                ldsm_x4(aAddr + (uint32_t)(arow << 7) + (uint32_t)(((kca ^ (arow & 7)) << 4)),
                        a[mt][0], a[mt][1], a[mt][2], a[mt][3]);
            }
            const int kcb = 2 * ks + bkc_half;
            uint32_t b[4][4];
            #pragma unroll
            for (int p = 0; p < 4; p++) {
                const int brow = brow_base + p * 16;
                ldsm_x4(bAddr + (uint32_t)(brow << 7) + (uint32_t)(((kcb ^ (brow & 7)) << 4)),
                        b[p][0], b[p][1], b[p][2], b[p][3]);
            }
            #pragma unroll
            for (int mt = 0; mt < 4; mt++)
                #pragma unroll
                for (int p = 0; p < 4; p++) {
                    mma_bf16(acc[mt][2 * p + 0], a[mt], &b[p][0]);
                    mma_bf16(acc[mt][2 * p + 1], a[mt], &b[p][2]);
                }
        }
    };

    load_ss(0, 0);
    for (int ss = 0; ss < NSS; ss++) {
        const int bsel = ss & 1;
        if (ss + 1 < NSS) load_ss(ss + 1, bsel ^ 1);   // other buffer: free
        else              load_w2();                    // buffer 0 free (ss=15)
        cp_wait<1>();        // newest = load just issued; ss's load complete
        __syncthreads();     // publish ss to all warps
        uint32_t B = buf[bsel];
        compute_chunk(B, B + 16384);
        if (ss < 8) compute_chunk(B, B + 32768);
        __syncthreads();     // all warps done with this buffer before reuse
    }

    // ------- Fused epilogue: partial = relu(acc+b1) @ W2_slice -------
    cp_wait<0>();
    __syncthreads();
    const uint32_t sW = buf[0];

    const int grpID = lane >> 2;
    const int tg    = lane & 3;
    const int brow_lane = ((grp >> 1) << 3) + lrow;   // 0..15
    float* dst = g_tp[blockIdx.x * 2 + warp_n];

    #pragma unroll
    for (int mt = 0; mt < 4; mt++) {
        float t2[6][4];
        #pragma unroll
        for (int t = 0; t < 6; t++)
            #pragma unroll
            for (int q = 0; q < 4; q++) t2[t][q] = 0.0f;

        #pragma unroll
        for (int j = 0; j < 4; j++) {
            int colA = block_n + warp_n * 64 + 16 * j + tg * 2;
            float b00 = bias[colA],     b01 = bias[colA + 1];
            float b10 = bias[colA + 8], b11 = bias[colA + 9];
            float v00 = fmaxf(acc[mt][2 * j][0] + b00, 0.f);
            float v01 = fmaxf(acc[mt][2 * j][1] + b01, 0.f);
            float v02 = fmaxf(acc[mt][2 * j][2] + b00, 0.f);
            float v03 = fmaxf(acc[mt][2 * j][3] + b01, 0.f);
            float v10 = fmaxf(acc[mt][2 * j + 1][0] + b10, 0.f);
            float v11 = fmaxf(acc[mt][2 * j + 1][1] + b11, 0.f);
            float v12 = fmaxf(acc[mt][2 * j + 1][2] + b10, 0.f);
            float v13 = fmaxf(acc[mt][2 * j + 1][3] + b11, 0.f);

            uint32_t aHi[4], aLo[4];
            aHi[0] = pack_split(v00, v01, aLo[0]);
            aHi[1] = pack_split(v02, v03, aLo[1]);
            aHi[2] = pack_split(v10, v11, aLo[2]);
            aHi[3] = pack_split(v12, v13, aLo[3]);

            const int cfull = warp_n * 8 + 2 * j + bkc_half;   // 16B-chunk 0..15
            uint32_t bHi[3][4], bLo[3][4];
            #pragma unroll
            for (int p = 0; p < 3; p++) {
                const int brow = brow_lane + p * 16;
                uint32_t sw = (uint32_t)((cfull & 8) | ((cfull ^ (brow & 7)) & 7));
                uint32_t off = (uint32_t)(brow * 256) + (sw << 4);
                ldsm_x4(sW + off,         bHi[p][0], bHi[p][1], bHi[p][2], bHi[p][3]);
                ldsm_x4(sW + 12288 + off, bLo[p][0], bLo[p][1], bLo[p][2], bLo[p][3]);
            }
            #pragma unroll
            for (int p = 0; p < 3; p++) {
                mma_bf16(t2[2 * p + 0], aHi, &bHi[p][0]);
                mma_bf16(t2[2 * p + 1], aHi, &bHi[p][2]);
                mma_bf16(t2[2 * p + 0], aHi, &bLo[p][0]);
                mma_bf16(t2[2 * p + 1], aHi, &bLo[p][2]);
                mma_bf16(t2[2 * p + 0], aLo, &bHi[p][0]);
                mma_bf16(t2[2 * p + 1], aLo, &bHi[p][2]);
            }
        }

        const int r0 = block_m + warp_m * 64 + mt * 16 + grpID;
        const int r1 = r0 + 8;
        #pragma unroll
        for (int t = 0; t < 6; t++) {
            const int col = t * 8 + tg * 2;
            if (r0 < NNODES) stcs_f2(&dst[(size_t)r0 * NCP + col], t2[t][0], t2[t][1]);
            if (r1 < NNODES) stcs_f2(&dst[(size_t)r1 * NCP + col], t2[t][2], t2[t][3]);
        }
    }
}

// combine the 32 partial slices: g_t[r, 0..39] = sum_z g_tp[z][r, 0..39]
__global__ void combine_kernel() {
    int idx = blockIdx.x * blockDim.x + threadIdx.x;   // over NNODES * 10
    if (idx >= NNODES * 10) return;
    int r = idx / 10, q = idx % 10;
    float4 s = make_float4(0.f, 0.f, 0.f, 0.f);
    #pragma unroll
    for (int z = 0; z < 32; z++) {
        float4 v = *(const float4*)&g_tp[z][(size_t)r * NCP + q * 4];
        s.x += v.x; s.y += v.y; s.z += v.z; s.w += v.w;
    }
    *(float4*)&g_t[(size_t)r * NCLS + q * 4] = s;
}

// ---------------------------------------------------------------------------
// Layer-2 propagate + bias
// ---------------------------------------------------------------------------
__global__ void gather2_kernel(const float* __restrict__ b2, float* __restrict__ out) {
    int gw = (blockIdx.x * blockDim.x + threadIdx.x) >> 5;
    int lane = threadIdx.x & 31;
    if (gw >= NNODES) return;
    int i = gw;
    float di = g_dinv[i];
    float self = di * di;
    int c1 = lane + 32;
    float acc0 = 0.f, acc1 = 0.f;
    int beg = g_rowptr[i], end = g_rowptr[i + 1];
    for (int j = beg; j < end; j++) {
        int s = g_csr_src[j];
        float c = g_csr_coef[j];
        acc0 += c * g_t[(size_t)s * NCLS + lane];
        if (lane < 8) acc1 += c * g_t[(size_t)s * NCLS + c1];
    }
    out[(size_t)i * NCLS + lane] = acc0 + self * g_t[(size_t)i * NCLS + lane] + b2[lane];
    if (lane < 8)
        out[(size_t)i * NCLS + c1] = acc1 + self * g_t[(size_t)i * NCLS + c1] + b2[c1];
}

// ---------------------------------------------------------------------------
// Entry point
// ---------------------------------------------------------------------------
extern "C" void kernel_launch(void* const* d_in, const int* in_sizes, int n_in,
                              void* d_out, int out_size) {
    const float* x   = (const float*)d_in[0];
    const int*   ei  = (const int*)d_in[1];
    const float* W1  = (const float*)d_in[2];
    const float* b1  = (const float*)d_in[3];
    const float* W2  = (const float*)d_in[4];
    const float* b2  = (const float*)d_in[5];
    float*       out = (float*)d_out;

    const int* src = ei;
    const int* dst = ei + NEDGES;

    cudaFuncSetAttribute(gemm_fused_kernel,
                         cudaFuncAttributeMaxDynamicSharedMemorySize, GEMM1_SMEM);

    // Fused init (W2' + W1' prep + degree count; g_cnt enters zeroed)
    prep_init_kernel<<<PREP_TOTAL_BLOCKS, 256>>>(W1, W2, dst);
    scan_kernel<<<1, 1024>>>();
    fill_kernel<<<(NEDGES + 255) / 256, 256>>>(src, dst);

    // Layer 1 + fused layer-2 GEMM
    gather1_kernel<<<NNODES, 128>>>(x);
    {
        dim3 grid(DHID / BN, GA_ROWS / BM);   // (16, 79)
        gemm_fused_kernel<<<grid, 128, GEMM1_SMEM>>>(b1);
    }

    // Combine partials, then layer-2 propagate
    combine_kernel<<<(NNODES * 10 + 255) / 256, 256>>>();
    gather2_kernel<<<(NNODES * 32 + 127) / 128, 128>>>(b2, out);
}